// round 11
// baseline (speedup 1.0000x reference)
#include <cuda_runtime.h>

// y = s1 * FWHT( g * FWHT( s2 * x ) ) per token, D = 4096.
// R0 dataflow (proven, 90.6us) but processing TWO tokens per register pair
// using Blackwell packed f32x2 math (FADD2/FFMA2/FMUL2). Both tokens share
// every sign, address, and transform -> all butterflies, sign-FMAs and
// elementwise scales are packed; exchanges are STS.64/LDS.64.

#define DDIM 4096
#define PAIRS 4           // token-pairs per CTA -> 8 tokens/CTA
#define NEG1 0xBF800000BF800000ULL

typedef unsigned long long u64;

__device__ __forceinline__ u64 pk2(float lo, float hi) {
    u64 u; asm("mov.b64 %0,{%1,%2};" : "=l"(u) : "f"(lo), "f"(hi)); return u;
}
__device__ __forceinline__ void up2(u64 u, float& a, float& b) {
    asm("mov.b64 {%0,%1},%2;" : "=f"(a), "=f"(b) : "l"(u));
}
__device__ __forceinline__ u64 add2(u64 a, u64 b) {
    u64 r; asm("add.rn.f32x2 %0,%1,%2;" : "=l"(r) : "l"(a), "l"(b)); return r;
}
__device__ __forceinline__ u64 mul2(u64 a, u64 b) {
    u64 r; asm("mul.rn.f32x2 %0,%1,%2;" : "=l"(r) : "l"(a), "l"(b)); return r;
}
__device__ __forceinline__ u64 fma2(u64 a, u64 b, u64 c) {
    u64 r; asm("fma.rn.f32x2 %0,%1,%2,%3;" : "=l"(r) : "l"(a), "l"(b), "l"(c)); return r;
}
// packed butterfly: (a,c) -> (a+c, a-c) for both tokens
__device__ __forceinline__ void bstep(u64& a, u64& c) {
    u64 s = add2(a, c);
    u64 d = fma2(c, NEG1, a);
    a = s; c = d;
}

__device__ __forceinline__ float softplus_f(float x) {
    return fmaxf(x, 0.0f) + log1pf(expf(-fabsf(x)));
}

__global__ void __launch_bounds__(256, 3)
whvi_kernel(const float* __restrict__ x,
            const float* __restrict__ s1,
            const float* __restrict__ s2,
            const float* __restrict__ g_mu,
            const float* __restrict__ g_rho,
            const float* __restrict__ eps,
            float* __restrict__ out,
            int n_tokens)
{
    __shared__ u64   sh2[DDIM];    // 32 KB packed exchange buffer
    __shared__ float gbuf[DDIM];   // 16 KB g_tilde (linear)

    const int t = threadIdx.x;     // 0..255
    const int l = t & 31;          // lane = element bits 0..4
    const int w = t >> 5;          // warp = element bits 9..11 (L1 layout)

    // ---- g_tilde once per CTA ----
#pragma unroll
    for (int r = 0; r < 16; r++) {
        const int i = t + (r << 8);
        gbuf[i] = g_mu[i] + softplus_f(g_rho[i]) * eps[i];
    }
    // ordered before first read by token-0's exchange-1 barrier

    const int tokA0 = blockIdx.x * (2 * PAIRS);

    for (int ip = 0; ip < PAIRS; ip++) {
        const int tokA = tokA0 + 2 * ip;
        if (tokA >= n_tokens) break;
        const int  tokB = tokA + 1;
        const bool hasB = (tokB < n_tokens);

        const float* __restrict__ xA = x + (size_t)tokA * DDIM;
        const float* __restrict__ xB = hasB ? x + (size_t)tokB * DDIM : xA;

        // ---- load both tokens, * s2, pack ----  (L0: elem i = t + 256r)
        u64 U[16];
#pragma unroll
        for (int r = 0; r < 16; r++) {
            const int i = t + (r << 8);
            const float s = s2[i];
            U[r] = pk2(xA[i] * s, xB[i] * s);
        }

        // ---- FWHT1 register stages: bits 8..11 ----
#pragma unroll
        for (int b = 1; b < 16; b <<= 1)
#pragma unroll
            for (int r = 0; r < 16; r++)
                if (!(r & b)) bstep(U[r], U[r | b]);

        // ---- FWHT1 shuffle stages: bits 0..4 ----
#pragma unroll
        for (int s = 0; s < 5; s++) {
            const int m = 1 << s;
            const float sg = (l & m) ? -1.0f : 1.0f;
            const u64 sg2 = pk2(sg, sg);
#pragma unroll
            for (int r = 0; r < 16; r++) {
                float a, b; up2(U[r], a, b);
                const float pa = __shfl_xor_sync(0xffffffffu, a, m);
                const float pb = __shfl_xor_sync(0xffffffffu, b, m);
                U[r] = fma2(U[r], sg2, pk2(pa, pb));
            }
        }

        // ---- exchange 1: L0 -> L1 (STS.64 / LDS.64) ----
        __syncthreads();
#pragma unroll
        for (int r = 0; r < 16; r++) sh2[t + (r << 8)] = U[r];
        __syncthreads();
#pragma unroll
        for (int p = 0; p < 2; p++)
#pragma unroll
            for (int k = 0; k < 8; k++)
                U[(p << 3) | k] = sh2[l + (k << 5) + (((w << 1) + p) << 8)];

        // ---- FWHT1 bits 5..7 ----
#pragma unroll
        for (int b = 1; b < 8; b <<= 1)
#pragma unroll
            for (int p = 0; p < 2; p++)
#pragma unroll
                for (int k = 0; k < 8; k++)
                    if (!(k & b)) bstep(U[(p << 3) | k], U[(p << 3) | k | b]);

        // ---- * g_tilde ----
#pragma unroll
        for (int p = 0; p < 2; p++)
#pragma unroll
            for (int k = 0; k < 8; k++) {
                const float g = gbuf[l + (k << 5) + (((w << 1) + p) << 8)];
                U[(p << 3) | k] = mul2(U[(p << 3) | k], pk2(g, g));
            }

        // ---- FWHT2 bits 5..7 ----
#pragma unroll
        for (int b = 1; b < 8; b <<= 1)
#pragma unroll
            for (int p = 0; p < 2; p++)
#pragma unroll
                for (int k = 0; k < 8; k++)
                    if (!(k & b)) bstep(U[(p << 3) | k], U[(p << 3) | k | b]);

        // ---- FWHT2 bit 8 (p) ----
#pragma unroll
        for (int k = 0; k < 8; k++) bstep(U[k], U[8 | k]);

        // ---- FWHT2 shuffle stages: bits 0..4 ----
#pragma unroll
        for (int s = 0; s < 5; s++) {
            const int m = 1 << s;
            const float sg = (l & m) ? -1.0f : 1.0f;
            const u64 sg2 = pk2(sg, sg);
#pragma unroll
            for (int r = 0; r < 16; r++) {
                float a, b; up2(U[r], a, b);
                const float pa = __shfl_xor_sync(0xffffffffu, a, m);
                const float pb = __shfl_xor_sync(0xffffffffu, b, m);
                U[r] = fma2(U[r], sg2, pk2(pa, pb));
            }
        }

        // ---- exchange 2: L1 -> L2 ----
        __syncthreads();
#pragma unroll
        for (int p = 0; p < 2; p++)
#pragma unroll
            for (int k = 0; k < 8; k++)
                sh2[l + (k << 5) + (((w << 1) + p) << 8)] = U[(p << 3) | k];
        __syncthreads();
#pragma unroll
        for (int p = 0; p < 2; p++)
#pragma unroll
            for (int j = 0; j < 8; j++)
                U[(j << 1) | p] = sh2[t + (p << 8) + (j << 9)];

        // ---- FWHT2 register stages: bits 9..11 (j) ----
#pragma unroll
        for (int b = 1; b < 8; b <<= 1)
#pragma unroll
            for (int p = 0; p < 2; p++)
#pragma unroll
                for (int j = 0; j < 8; j++)
                    if (!(j & b)) bstep(U[(j << 1) | p], U[((j | b) << 1) | p]);

        // ---- * s1, unpack, store both tokens (coalesced) ----
        float* __restrict__ oA = out + (size_t)tokA * DDIM;
        float* __restrict__ oB = out + (size_t)tokB * DDIM;
#pragma unroll
        for (int p = 0; p < 2; p++)
#pragma unroll
            for (int j = 0; j < 8; j++) {
                const int i = t + (p << 8) + (j << 9);
                const float s = s1[i];
                float a, b; up2(U[(j << 1) | p], a, b);
                oA[i] = a * s;
                if (hasB) oB[i] = b * s;
            }
    }
}

extern "C" void kernel_launch(void* const* d_in, const int* in_sizes, int n_in,
                              void* d_out, int out_size)
{
    const float* x     = (const float*)d_in[0];
    const float* s1    = (const float*)d_in[1];
    const float* s2    = (const float*)d_in[2];
    const float* g_mu  = (const float*)d_in[3];
    const float* g_rho = (const float*)d_in[4];
    const float* eps   = (const float*)d_in[5];
    // d_in[6] = H, unused

    float* out = (float*)d_out;
    const int n_tokens = in_sizes[0] / DDIM;
    const int per_cta = 2 * PAIRS;
    const int grid = (n_tokens + per_cta - 1) / per_cta;

    whvi_kernel<<<grid, 256>>>(x, s1, s2, g_mu, g_rho, eps, out, n_tokens);
}

// round 12
// speedup vs baseline: 1.0007x; 1.0007x over previous
#include <cuda_runtime.h>

// y = s1 * FWHT( g * FWHT( s2 * x ) ) per token, D = 4096.
// R0 dataflow (proven, 90.6us) but processing TWO tokens per register pair
// using Blackwell packed f32x2 math (FADD2/FFMA2/FMUL2). Both tokens share
// every sign, address, and transform -> all butterflies, sign-FMAs and
// elementwise scales are packed; exchanges are STS.64/LDS.64.

#define DDIM 4096
#define PAIRS 4           // token-pairs per CTA -> 8 tokens/CTA
#define NEG1 0xBF800000BF800000ULL

typedef unsigned long long u64;

__device__ __forceinline__ u64 pk2(float lo, float hi) {
    u64 u; asm("mov.b64 %0,{%1,%2};" : "=l"(u) : "f"(lo), "f"(hi)); return u;
}
__device__ __forceinline__ void up2(u64 u, float& a, float& b) {
    asm("mov.b64 {%0,%1},%2;" : "=f"(a), "=f"(b) : "l"(u));
}
__device__ __forceinline__ u64 add2(u64 a, u64 b) {
    u64 r; asm("add.rn.f32x2 %0,%1,%2;" : "=l"(r) : "l"(a), "l"(b)); return r;
}
__device__ __forceinline__ u64 mul2(u64 a, u64 b) {
    u64 r; asm("mul.rn.f32x2 %0,%1,%2;" : "=l"(r) : "l"(a), "l"(b)); return r;
}
__device__ __forceinline__ u64 fma2(u64 a, u64 b, u64 c) {
    u64 r; asm("fma.rn.f32x2 %0,%1,%2,%3;" : "=l"(r) : "l"(a), "l"(b), "l"(c)); return r;
}
// packed butterfly: (a,c) -> (a+c, a-c) for both tokens
__device__ __forceinline__ void bstep(u64& a, u64& c) {
    u64 s = add2(a, c);
    u64 d = fma2(c, NEG1, a);
    a = s; c = d;
}

__device__ __forceinline__ float softplus_f(float x) {
    return fmaxf(x, 0.0f) + log1pf(expf(-fabsf(x)));
}

__global__ void __launch_bounds__(256, 3)
whvi_kernel(const float* __restrict__ x,
            const float* __restrict__ s1,
            const float* __restrict__ s2,
            const float* __restrict__ g_mu,
            const float* __restrict__ g_rho,
            const float* __restrict__ eps,
            float* __restrict__ out,
            int n_tokens)
{
    __shared__ u64   sh2[DDIM];    // 32 KB packed exchange buffer
    __shared__ float gbuf[DDIM];   // 16 KB g_tilde (linear)

    const int t = threadIdx.x;     // 0..255
    const int l = t & 31;          // lane = element bits 0..4
    const int w = t >> 5;          // warp = element bits 9..11 (L1 layout)

    // ---- g_tilde once per CTA ----
#pragma unroll
    for (int r = 0; r < 16; r++) {
        const int i = t + (r << 8);
        gbuf[i] = g_mu[i] + softplus_f(g_rho[i]) * eps[i];
    }
    // ordered before first read by token-0's exchange-1 barrier

    const int tokA0 = blockIdx.x * (2 * PAIRS);

    for (int ip = 0; ip < PAIRS; ip++) {
        const int tokA = tokA0 + 2 * ip;
        if (tokA >= n_tokens) break;
        const int  tokB = tokA + 1;
        const bool hasB = (tokB < n_tokens);

        const float* __restrict__ xA = x + (size_t)tokA * DDIM;
        const float* __restrict__ xB = hasB ? x + (size_t)tokB * DDIM : xA;

        // ---- load both tokens, * s2, pack ----  (L0: elem i = t + 256r)
        u64 U[16];
#pragma unroll
        for (int r = 0; r < 16; r++) {
            const int i = t + (r << 8);
            const float s = s2[i];
            U[r] = pk2(xA[i] * s, xB[i] * s);
        }

        // ---- FWHT1 register stages: bits 8..11 ----
#pragma unroll
        for (int b = 1; b < 16; b <<= 1)
#pragma unroll
            for (int r = 0; r < 16; r++)
                if (!(r & b)) bstep(U[r], U[r | b]);

        // ---- FWHT1 shuffle stages: bits 0..4 ----
#pragma unroll
        for (int s = 0; s < 5; s++) {
            const int m = 1 << s;
            const float sg = (l & m) ? -1.0f : 1.0f;
            const u64 sg2 = pk2(sg, sg);
#pragma unroll
            for (int r = 0; r < 16; r++) {
                float a, b; up2(U[r], a, b);
                const float pa = __shfl_xor_sync(0xffffffffu, a, m);
                const float pb = __shfl_xor_sync(0xffffffffu, b, m);
                U[r] = fma2(U[r], sg2, pk2(pa, pb));
            }
        }

        // ---- exchange 1: L0 -> L1 (STS.64 / LDS.64) ----
        __syncthreads();
#pragma unroll
        for (int r = 0; r < 16; r++) sh2[t + (r << 8)] = U[r];
        __syncthreads();
#pragma unroll
        for (int p = 0; p < 2; p++)
#pragma unroll
            for (int k = 0; k < 8; k++)
                U[(p << 3) | k] = sh2[l + (k << 5) + (((w << 1) + p) << 8)];

        // ---- FWHT1 bits 5..7 ----
#pragma unroll
        for (int b = 1; b < 8; b <<= 1)
#pragma unroll
            for (int p = 0; p < 2; p++)
#pragma unroll
                for (int k = 0; k < 8; k++)
                    if (!(k & b)) bstep(U[(p << 3) | k], U[(p << 3) | k | b]);

        // ---- * g_tilde ----
#pragma unroll
        for (int p = 0; p < 2; p++)
#pragma unroll
            for (int k = 0; k < 8; k++) {
                const float g = gbuf[l + (k << 5) + (((w << 1) + p) << 8)];
                U[(p << 3) | k] = mul2(U[(p << 3) | k], pk2(g, g));
            }

        // ---- FWHT2 bits 5..7 ----
#pragma unroll
        for (int b = 1; b < 8; b <<= 1)
#pragma unroll
            for (int p = 0; p < 2; p++)
#pragma unroll
                for (int k = 0; k < 8; k++)
                    if (!(k & b)) bstep(U[(p << 3) | k], U[(p << 3) | k | b]);

        // ---- FWHT2 bit 8 (p) ----
#pragma unroll
        for (int k = 0; k < 8; k++) bstep(U[k], U[8 | k]);

        // ---- FWHT2 shuffle stages: bits 0..4 ----
#pragma unroll
        for (int s = 0; s < 5; s++) {
            const int m = 1 << s;
            const float sg = (l & m) ? -1.0f : 1.0f;
            const u64 sg2 = pk2(sg, sg);
#pragma unroll
            for (int r = 0; r < 16; r++) {
                float a, b; up2(U[r], a, b);
                const float pa = __shfl_xor_sync(0xffffffffu, a, m);
                const float pb = __shfl_xor_sync(0xffffffffu, b, m);
                U[r] = fma2(U[r], sg2, pk2(pa, pb));
            }
        }

        // ---- exchange 2: L1 -> L2 ----
        __syncthreads();
#pragma unroll
        for (int p = 0; p < 2; p++)
#pragma unroll
            for (int k = 0; k < 8; k++)
                sh2[l + (k << 5) + (((w << 1) + p) << 8)] = U[(p << 3) | k];
        __syncthreads();
#pragma unroll
        for (int p = 0; p < 2; p++)
#pragma unroll
            for (int j = 0; j < 8; j++)
                U[(j << 1) | p] = sh2[t + (p << 8) + (j << 9)];

        // ---- FWHT2 register stages: bits 9..11 (j) ----
#pragma unroll
        for (int b = 1; b < 8; b <<= 1)
#pragma unroll
            for (int p = 0; p < 2; p++)
#pragma unroll
                for (int j = 0; j < 8; j++)
                    if (!(j & b)) bstep(U[(j << 1) | p], U[((j | b) << 1) | p]);

        // ---- * s1, unpack, store both tokens (coalesced) ----
        float* __restrict__ oA = out + (size_t)tokA * DDIM;
        float* __restrict__ oB = out + (size_t)tokB * DDIM;
#pragma unroll
        for (int p = 0; p < 2; p++)
#pragma unroll
            for (int j = 0; j < 8; j++) {
                const int i = t + (p << 8) + (j << 9);
                const float s = s1[i];
                float a, b; up2(U[(j << 1) | p], a, b);
                oA[i] = a * s;
                if (hasB) oB[i] = b * s;
            }
    }
}

extern "C" void kernel_launch(void* const* d_in, const int* in_sizes, int n_in,
                              void* d_out, int out_size)
{
    const float* x     = (const float*)d_in[0];
    const float* s1    = (const float*)d_in[1];
    const float* s2    = (const float*)d_in[2];
    const float* g_mu  = (const float*)d_in[3];
    const float* g_rho = (const float*)d_in[4];
    const float* eps   = (const float*)d_in[5];
    // d_in[6] = H, unused

    float* out = (float*)d_out;
    const int n_tokens = in_sizes[0] / DDIM;
    const int per_cta = 2 * PAIRS;
    const int grid = (n_tokens + per_cta - 1) / per_cta;

    whvi_kernel<<<grid, 256>>>(x, s1, s2, g_mu, g_rho, eps, out, n_tokens);
}

// round 13
// speedup vs baseline: 1.0194x; 1.0187x over previous
#include <cuda_runtime.h>

// y = s1 * FWHT( g * FWHT( s2 * x ) ) per token, D = 4096.
// Two tokens per register pair (Blackwell f32x2 packed math), 16 u64/thread.
// Schedule with only 8 shuffle stages (bits i0-3, twice) instead of 10:
//   L0: regs i8-11, lanes i0-4, warps i5-7      (coalesced global I/O)
//   L1: regs i4-7,  lanes {i0-3, i8}, warps i9-11
// FWHT1 = bfly4(i8-11) . X1 . bfly4(i4-7) . shfl(i0-3)
// *g, FWHT2 = shfl(i0-3) . bfly4(i4-7) . X2 . bfly4(i8-11)
// One injective XOR map serves both exchanges and the g buffer:
//   sigma(i) = i0_3 | (i4^i8)<<4 | i5_7<<5 | i8<<8 | i9_11<<9
// Bank-bijective on both sides (verified per access pattern).

#define DDIM 4096
#define PAIRS 4           // token-pairs per CTA -> 8 tokens/CTA
#define NEG1 0xBF800000BF800000ULL

typedef unsigned long long u64;

__device__ __forceinline__ u64 pk2(float lo, float hi) {
    u64 u; asm("mov.b64 %0,{%1,%2};" : "=l"(u) : "f"(lo), "f"(hi)); return u;
}
__device__ __forceinline__ void up2(u64 u, float& a, float& b) {
    asm("mov.b64 {%0,%1},%2;" : "=f"(a), "=f"(b) : "l"(u));
}
__device__ __forceinline__ u64 add2(u64 a, u64 b) {
    u64 r; asm("add.rn.f32x2 %0,%1,%2;" : "=l"(r) : "l"(a), "l"(b)); return r;
}
__device__ __forceinline__ u64 mul2(u64 a, u64 b) {
    u64 r; asm("mul.rn.f32x2 %0,%1,%2;" : "=l"(r) : "l"(a), "l"(b)); return r;
}
__device__ __forceinline__ u64 fma2(u64 a, u64 b, u64 c) {
    u64 r; asm("fma.rn.f32x2 %0,%1,%2,%3;" : "=l"(r) : "l"(a), "l"(b), "l"(c)); return r;
}
// packed butterfly: (a,c) -> (a+c, a-c) for both tokens
__device__ __forceinline__ void bstep(u64& a, u64& c) {
    u64 s = add2(a, c);
    u64 d = fma2(c, NEG1, a);
    a = s; c = d;
}
// full 4-bit FWHT over U[16] (reg index = the 4 bits)
__device__ __forceinline__ void bfly4p(u64 U[16]) {
#pragma unroll
    for (int b = 1; b < 16; b <<= 1)
#pragma unroll
        for (int r = 0; r < 16; r++)
            if (!(r & b)) bstep(U[r], U[r | b]);
}

__device__ __forceinline__ float softplus_f(float x) {
    return fmaxf(x, 0.0f) + log1pf(expf(-fabsf(x)));
}

__global__ void __launch_bounds__(256, 3)
whvi_kernel(const float* __restrict__ x,
            const float* __restrict__ s1,
            const float* __restrict__ s2,
            const float* __restrict__ g_mu,
            const float* __restrict__ g_rho,
            const float* __restrict__ eps,
            float* __restrict__ out,
            int n_tokens)
{
    __shared__ u64   sh2[DDIM];    // 32 KB packed exchange buffer (sigma addresses)
    __shared__ float gbuf[DDIM];   // 16 KB g_tilde at sigma addresses

    const int t = threadIdx.x;     // 0..255 ; L0: t = i0-7
    const int l = t & 31;          // lane
    const int w = t >> 5;          // warp (L1: = i9-11)

    // sigma bases:
    //  L0 side: addr(r) = t ^ ((r&1)*0x110) ^ ((r>>1)<<9)       (r = i8-11)
    //  L1 side: addr(r) = rb ^ (r<<4)                           (r = i4-7)
    const int rb = (l & 15) | ((l >> 4) << 4) | ((l >> 4) << 8) | (w << 9);

    // ---- g_tilde once per CTA, stored at sigma (L1-side) addresses ----
#pragma unroll
    for (int r = 0; r < 16; r++) {
        const int i = (l & 15) | (r << 4) | ((l >> 4) << 8) | (w << 9);
        gbuf[rb ^ (r << 4)] = g_mu[i] + softplus_f(g_rho[i]) * eps[i];
    }
    // visible before first read via pair-0's X1 barriers

    const int tokA0 = blockIdx.x * (2 * PAIRS);

    for (int ip = 0; ip < PAIRS; ip++) {
        const int tokA = tokA0 + 2 * ip;
        if (tokA >= n_tokens) break;
        const int  tokB = tokA + 1;
        const bool hasB = (tokB < n_tokens);

        const float* __restrict__ xA = x + (size_t)tokA * DDIM;
        const float* __restrict__ xB = hasB ? x + (size_t)tokB * DDIM : xA;

        // ---- load both tokens, * s2, pack ----  (L0: elem i = t + 256r)
        u64 U[16];
#pragma unroll
        for (int r = 0; r < 16; r++) {
            const int i = t + (r << 8);
            const float s = s2[i];
            U[r] = pk2(xA[i] * s, xB[i] * s);
        }

        bfly4p(U);                                  // FWHT1 bits 8-11

        // ---- X1: L0 -> L1 ----
        __syncthreads();                            // WAR vs prev pair X2 reads
#pragma unroll
        for (int r = 0; r < 16; r++)
            sh2[t ^ ((r & 1) * 0x110) ^ ((r >> 1) << 9)] = U[r];
        __syncthreads();
#pragma unroll
        for (int r = 0; r < 16; r++)
            U[r] = sh2[rb ^ (r << 4)];

        bfly4p(U);                                  // FWHT1 bits 4-7

        // ---- FWHT1 shuffles: bits 0-3 (lane masks 1,2,4,8) ----
#pragma unroll
        for (int s = 0; s < 4; s++) {
            const int m = 1 << s;
            const float sg = (l & m) ? -1.0f : 1.0f;
            const u64 sg2 = pk2(sg, sg);
#pragma unroll
            for (int r = 0; r < 16; r++) {
                float a, b; up2(U[r], a, b);
                const float pa = __shfl_xor_sync(0xffffffffu, a, m);
                const float pb = __shfl_xor_sync(0xffffffffu, b, m);
                U[r] = fma2(U[r], sg2, pk2(pa, pb));
            }
        }

        // ---- * g_tilde (sigma addresses, conflict-free) ----
#pragma unroll
        for (int r = 0; r < 16; r++) {
            const float g = gbuf[rb ^ (r << 4)];
            U[r] = mul2(U[r], pk2(g, g));
        }

        // ---- FWHT2 shuffles: bits 0-3 ----
#pragma unroll
        for (int s = 0; s < 4; s++) {
            const int m = 1 << s;
            const float sg = (l & m) ? -1.0f : 1.0f;
            const u64 sg2 = pk2(sg, sg);
#pragma unroll
            for (int r = 0; r < 16; r++) {
                float a, b; up2(U[r], a, b);
                const float pa = __shfl_xor_sync(0xffffffffu, a, m);
                const float pb = __shfl_xor_sync(0xffffffffu, b, m);
                U[r] = fma2(U[r], sg2, pk2(pa, pb));
            }
        }

        bfly4p(U);                                  // FWHT2 bits 4-7

        // ---- X2: L1 -> L0 ----
        __syncthreads();                            // WAR vs X1 reads
#pragma unroll
        for (int r = 0; r < 16; r++)
            sh2[rb ^ (r << 4)] = U[r];
        __syncthreads();
#pragma unroll
        for (int r = 0; r < 16; r++)
            U[r] = sh2[t ^ ((r & 1) * 0x110) ^ ((r >> 1) << 9)];

        bfly4p(U);                                  // FWHT2 bits 8-11

        // ---- * s1, unpack, store both tokens (coalesced) ----
        float* __restrict__ oA = out + (size_t)tokA * DDIM;
        float* __restrict__ oB = out + (size_t)tokB * DDIM;
#pragma unroll
        for (int r = 0; r < 16; r++) {
            const int i = t + (r << 8);
            const float s = s1[i];
            float a, b; up2(U[r], a, b);
            oA[i] = a * s;
            if (hasB) oB[i] = b * s;
        }
    }
}

extern "C" void kernel_launch(void* const* d_in, const int* in_sizes, int n_in,
                              void* d_out, int out_size)
{
    const float* x     = (const float*)d_in[0];
    const float* s1    = (const float*)d_in[1];
    const float* s2    = (const float*)d_in[2];
    const float* g_mu  = (const float*)d_in[3];
    const float* g_rho = (const float*)d_in[4];
    const float* eps   = (const float*)d_in[5];
    // d_in[6] = H, unused

    float* out = (float*)d_out;
    const int n_tokens = in_sizes[0] / DDIM;
    const int per_cta = 2 * PAIRS;
    const int grid = (n_tokens + per_cta - 1) / per_cta;

    whvi_kernel<<<grid, 256>>>(x, s1, s2, g_mu, g_rho, eps, out, n_tokens);
}